// round 4
// baseline (speedup 1.0000x reference)
#include <cuda_runtime.h>
typedef unsigned long long u64;

// B=32, CIN=COUT=32, H=W=128, M1=M2=16, NMODE=32.
__device__ float2 g_Xw[1024 * 2048];   // [bc][h][ky]  16 MB
__device__ float2 g_Xf[512 * 1024];    // [f][bc]       4 MB
__device__ float2 g_Yf[1024 * 512];    // [bo][f]       4 MB

// Twiddle tables: f32x2 pairs.
__device__ u64 tC1[1024], tS1[1024];    // [w][p]   p: ky pair (2p,2p+1), fwd W-DFT
__device__ u64 tE2r[2048], tE2i[2048];  // [h][q]   q: kx pair, fwd H-DFT (e^{-i})
__device__ u64 tE3r[2048], tE3i[2048];  // [kxi][hp] hp: h pair, inv H-DFT (e^{+i})
__device__ u64 tB4[2048];               // [j][wp]  j=2k+comp, inv W (scaled, signed)

__device__ __forceinline__ u64 f2pack(float a, float b) {
    u64 r; asm("mov.b64 %0,{%1,%2};" : "=l"(r) : "f"(a), "f"(b)); return r;
}
__device__ __forceinline__ u64 splat(float a) {
    u64 r; asm("mov.b64 %0,{%1,%1};" : "=l"(r) : "f"(a)); return r;
}
__device__ __forceinline__ float2 f2unpack(u64 v) {
    float2 r; asm("mov.b64 {%0,%1},%2;" : "=f"(r.x), "=f"(r.y) : "l"(v)); return r;
}
__device__ __forceinline__ u64 fma2(u64 a, u64 b, u64 c) {
    u64 d; asm("fma.rn.f32x2 %0,%1,%2,%3;" : "=l"(d) : "l"(a), "l"(b), "l"(c)); return d;
}

// ---------------- k0: build tables (7168 pair entries) ----------------
__global__ void k0_tables() {
    int id = blockIdx.x * 256 + threadIdx.x;
    float s0, c0, s1, c1;
    if (id < 1024) {                       // tC1/tS1: [w][p]
        int w = id >> 3, p = id & 7;
        sincospif((float)((2 * p)     * w) / 64.f, &s0, &c0);
        sincospif((float)((2 * p + 1) * w) / 64.f, &s1, &c1);
        tC1[id] = f2pack(c0, c1); tS1[id] = f2pack(-s0, -s1);
    } else if (id < 3072) {                // tE2: [h][q], kx pair (2q,2q+1)
        int e = id - 1024; int h = e >> 4, q = e & 15;
        int ka = (2 * q)     < 16 ? 2 * q     : 2 * q + 96;
        int kb = (2 * q + 1) < 16 ? 2 * q + 1 : 2 * q + 1 + 96;
        sincospif((float)(ka * h) / 64.f, &s0, &c0);
        sincospif((float)(kb * h) / 64.f, &s1, &c1);
        tE2r[e] = f2pack(c0, c1); tE2i[e] = f2pack(-s0, -s1);
    } else if (id < 5120) {                // tE3: [kxi][hp], h pair (2hp,2hp+1)
        int e = id - 3072; int kxi = e >> 6, hp = e & 63;
        int ka = kxi < 16 ? kxi : kxi + 96;
        sincospif((float)(ka * (2 * hp))     / 64.f, &s0, &c0);
        sincospif((float)(ka * (2 * hp + 1)) / 64.f, &s1, &c1);
        tE3r[e] = f2pack(c0, c1); tE3i[e] = f2pack(s0, s1);
    } else if (id < 7168) {                // tB4: [j][wp], j=2k+comp
        int e = id - 5120; int j = e >> 6, wp = e & 63;
        int k = j >> 1, comp = j & 1;
        float sc = (k == 0 ? 1.f : 2.f) / 16384.f;
        sincospif((float)(k * (2 * wp))     / 64.f, &s0, &c0);
        sincospif((float)(k * (2 * wp + 1)) / 64.f, &s1, &c1);
        tB4[e] = comp ? f2pack(-sc * s0, -sc * s1) : f2pack(sc * c0, sc * c1);
    }
}

// ---------------- k1: W-DFT. Xw[h][ky] = sum_w x[h][w] e^{-2pi i ky w/128} ----
// grid 512 (2 bc tiles/block). thread: 4 rows (rg+32i) x 4 ky (kyp pair pbase,pbase+1).
__global__ void __launch_bounds__(256, 2) k1_wdft(const float* __restrict__ x) {
    const int tid = threadIdx.x;
    const int sub = tid >> 7, t = tid & 127;
    const int kyq = t & 3, rg = t >> 2;            // rg 0..31
    const int bc  = blockIdx.x * 2 + sub;
    const int pb  = kyq * 2;
    const float4* xp = (const float4*)(x + (size_t)bc * 16384) + rg * 32;

    u64 aR[4][2], aI[4][2];
    #pragma unroll
    for (int i = 0; i < 4; i++) { aR[i][0]=aR[i][1]=aI[i][0]=aI[i][1]=0ull; }

    for (int w4 = 0; w4 < 32; w4++) {
        float4 v[4];
        v[0] = xp[w4]; v[1] = xp[1024 + w4]; v[2] = xp[2048 + w4]; v[3] = xp[3072 + w4];
        #pragma unroll
        for (int c = 0; c < 4; c++) {
            int w = w4 * 4 + c;
            u64 C0 = tC1[w * 8 + pb],     S0 = tS1[w * 8 + pb];
            u64 C1 = tC1[w * 8 + pb + 1], S1 = tS1[w * 8 + pb + 1];
            #pragma unroll
            for (int i = 0; i < 4; i++) {
                float f = (c == 0) ? v[i].x : (c == 1) ? v[i].y : (c == 2) ? v[i].z : v[i].w;
                u64 s = splat(f);
                aR[i][0] = fma2(s, C0, aR[i][0]); aI[i][0] = fma2(s, S0, aI[i][0]);
                aR[i][1] = fma2(s, C1, aR[i][1]); aI[i][1] = fma2(s, S1, aI[i][1]);
            }
        }
    }
    #pragma unroll
    for (int i = 0; i < 4; i++)
        #pragma unroll
        for (int p = 0; p < 2; p++) {
            float2 re = f2unpack(aR[i][p]), im = f2unpack(aI[i][p]);
            float2* o = g_Xw + (size_t)bc * 2048 + (rg + 32 * i) * 16 + 2 * (pb + p);
            o[0] = make_float2(re.x, im.x);
            o[1] = make_float2(re.y, im.y);
        }
}

// ---------------- k2: H-DFT. Xf[kxi][ky] = sum_h Xw[h][ky] e^{-2pi i kxa h/128} --
// grid 512 (2 bc tiles/block, 128 thr each). thread: 2 ky x 2 kx (pair q).
__global__ void __launch_bounds__(256) k2_hdft() {
    __shared__ float4 sV[2][1024];       // [h][kyp] = 2 complex
    const int tid = threadIdx.x;
    const int sub = tid >> 7, t = tid & 127;
    const int bc  = blockIdx.x * 2 + sub;

    const float4* src = (const float4*)(g_Xw + (size_t)bc * 2048);
    for (int i = t; i < 1024; i += 128) sV[sub][i] = src[i];
    __syncthreads();

    const int q = t & 15, kyp = t >> 4;
    u64 R0 = 0, I0 = 0, R1 = 0, I1 = 0;
    for (int h = 0; h < 128; h++) {
        float4 v = sV[sub][h * 8 + kyp];
        u64 er = tE2r[h * 16 + q], ei = tE2i[h * 16 + q];
        u64 xs = splat(v.x), ys = splat(v.y), yn = splat(-v.y);
        R0 = fma2(xs, er, R0); R0 = fma2(yn, ei, R0);
        I0 = fma2(xs, ei, I0); I0 = fma2(ys, er, I0);
        xs = splat(v.z); ys = splat(v.w); yn = splat(-v.w);
        R1 = fma2(xs, er, R1); R1 = fma2(yn, ei, R1);
        I1 = fma2(xs, ei, I1); I1 = fma2(ys, er, I1);
    }
    float2 r0 = f2unpack(R0), i0 = f2unpack(I0), r1 = f2unpack(R1), i1 = f2unpack(I1);
    const int ky0 = 2 * kyp;
    g_Xf[(size_t)((2 * q)     * 16 + ky0)     * 1024 + bc] = make_float2(r0.x, i0.x);
    g_Xf[(size_t)((2 * q + 1) * 16 + ky0)     * 1024 + bc] = make_float2(r0.y, i0.y);
    g_Xf[(size_t)((2 * q)     * 16 + ky0 + 1) * 1024 + bc] = make_float2(r1.x, i1.x);
    g_Xf[(size_t)((2 * q + 1) * 16 + ky0 + 1) * 1024 + bc] = make_float2(r1.y, i1.y);
}

// ---------------- k3: spectral mix per frequency ----------------
__global__ void __launch_bounds__(256) k3_mix(const float* __restrict__ wr,
                                              const float* __restrict__ wi) {
    __shared__ float2 Xs[1024], Ws[1024];
    const int f = blockIdx.x, kxi = f >> 4, kyy = f & 15;
    const int tid = threadIdx.x;
    for (int idx = tid; idx < 1024; idx += 256) {
        Xs[idx] = g_Xf[(size_t)f * 1024 + idx];
        int i = idx >> 5, o = idx & 31;
        int widx = ((i * 32 + o) * 32 + kxi) * 16 + kyy;
        Ws[idx] = make_float2(wr[widx], wi[widx]);
    }
    __syncthreads();
    const int o = tid & 31, bg = tid >> 5;
    float2 a[4];
    #pragma unroll
    for (int j = 0; j < 4; j++) a[j] = make_float2(0.f, 0.f);
    #pragma unroll 4
    for (int i = 0; i < 32; i++) {
        float2 wv = Ws[i * 32 + o];
        #pragma unroll
        for (int j = 0; j < 4; j++) {
            float2 xv = Xs[(bg + 8 * j) * 32 + i];
            a[j].x = fmaf(xv.x, wv.x, a[j].x); a[j].x = fmaf(-xv.y, wv.y, a[j].x);
            a[j].y = fmaf(xv.x, wv.y, a[j].y); a[j].y = fmaf( xv.y, wv.x, a[j].y);
        }
    }
    #pragma unroll
    for (int j = 0; j < 4; j++)
        g_Yf[(size_t)((bg + 8 * j) * 32 + o) * 512 + f] = a[j];
}

// ---------------- k4: inverse. grid 1024 (bo). ----------------
// Stage1: y1[h][ky] = sum_kxi Yf[kxi][ky] e^{+2pi i kxa h/128}  -> y1T[32][132]
// Stage2: real GEMM out[h][w] = sum_j y1T[j][h] * B4[j][w]
__global__ void __launch_bounds__(256) k4_inv(float* __restrict__ out) {
    __shared__ float2 sY[512];
    __shared__ float y1T[32 * 132];
    const int tid = threadIdx.x, bo = blockIdx.x;
    for (int i = tid; i < 512; i += 256) sY[i] = g_Yf[(size_t)bo * 512 + i];
    __syncthreads();
    {
        const int ky = tid & 15, hs = tid >> 4;
        u64 R[4] = {0, 0, 0, 0}, I[4] = {0, 0, 0, 0};
        for (int kxi = 0; kxi < 32; kxi++) {
            float2 v = sY[kxi * 16 + ky];
            u64 xs = splat(v.x), ys = splat(v.y), yn = splat(-v.y);
            #pragma unroll
            for (int j = 0; j < 4; j++) {
                int hp = hs + 16 * j;
                u64 er = tE3r[kxi * 64 + hp], ei = tE3i[kxi * 64 + hp];
                R[j] = fma2(xs, er, R[j]); R[j] = fma2(yn, ei, R[j]);
                I[j] = fma2(xs, ei, I[j]); I[j] = fma2(ys, er, I[j]);
            }
        }
        #pragma unroll
        for (int j = 0; j < 4; j++) {
            int hp = hs + 16 * j;
            *(float2*)(y1T + (2 * ky)     * 132 + 2 * hp) = f2unpack(R[j]);
            *(float2*)(y1T + (2 * ky + 1) * 132 + 2 * hp) = f2unpack(I[j]);
        }
    }
    __syncthreads();
    {
        const int ws = tid & 15, hg0 = tid >> 4;
        #pragma unroll
        for (int pass = 0; pass < 2; pass++) {
            const int h0 = (hg0 + 16 * pass) * 4;
            u64 acc[4][4];
            #pragma unroll
            for (int hi = 0; hi < 4; hi++)
                #pragma unroll
                for (int m = 0; m < 4; m++) acc[hi][m] = 0ull;
            for (int j = 0; j < 32; j++) {
                float4 a = *(const float4*)(y1T + j * 132 + h0);
                u64 a0 = splat(a.x), a1 = splat(a.y), a2 = splat(a.z), a3 = splat(a.w);
                #pragma unroll
                for (int m = 0; m < 4; m++) {
                    u64 b = tB4[j * 64 + ws + 16 * m];
                    acc[0][m] = fma2(a0, b, acc[0][m]);
                    acc[1][m] = fma2(a1, b, acc[1][m]);
                    acc[2][m] = fma2(a2, b, acc[2][m]);
                    acc[3][m] = fma2(a3, b, acc[3][m]);
                }
            }
            float* op = out + (size_t)bo * 16384;
            #pragma unroll
            for (int hi = 0; hi < 4; hi++)
                #pragma unroll
                for (int m = 0; m < 4; m++)
                    *(float2*)(op + (h0 + hi) * 128 + 2 * (ws + 16 * m)) = f2unpack(acc[hi][m]);
        }
    }
}

// ---------------------------------------------------------------------------
extern "C" void kernel_launch(void* const* d_in, const int* in_sizes, int n_in,
                              void* d_out, int out_size) {
    const float* x  = (const float*)d_in[0];
    const float* wr = (const float*)d_in[1];
    const float* wi = (const float*)d_in[2];
    float* out = (float*)d_out;

    k0_tables<<<28, 256>>>();
    k1_wdft<<<512, 256>>>(x);
    k2_hdft<<<512, 256>>>();
    k3_mix<<<512, 256>>>(wr, wi);
    k4_inv<<<1024, 256>>>(out);
}